// round 6
// baseline (speedup 1.0000x reference)
#include <cuda_runtime.h>
#include <cstddef>

#define BATCH 16
#define NVERT 250000
#define NFACE 500000
#define NADJ  (6 * NFACE)          // 3,000,000 adjacency entries
#define SCAN_B 1024
#define NBLK ((NVERT + SCAN_B - 1) / SCAN_B)   // 245
#define GW 32                      // warps (=vertices) per gather block

// ---------------------------------------------------------------------------
// Device scratch (static; no runtime allocation allowed)
// ---------------------------------------------------------------------------
__device__ int    g_deg[NVERT];
__device__ int    g_start[NVERT];
__device__ int    g_cursor[NVERT];
__device__ int2   g_adj2[NADJ / 2];                 // pairs (all offsets even)
__device__ int    g_blocksum[NBLK];
__device__ int    g_blockoff[NBLK];
// [v][b][xyz] packed float3 rows: 48 floats = 192 B per vertex, 48 MB total
__device__ float  g_vert3[(size_t)NVERT * BATCH * 3];

// ---------------------------------------------------------------------------
// 1. Zero degrees
// ---------------------------------------------------------------------------
__global__ void zero_deg_kernel() {
    int i = blockIdx.x * blockDim.x + threadIdx.x;
    if (i < NVERT) g_deg[i] = 0;
}

// ---------------------------------------------------------------------------
// 2. Count degrees
// ---------------------------------------------------------------------------
__global__ void count_deg_kernel(const int* __restrict__ faces) {
    int f = blockIdx.x * blockDim.x + threadIdx.x;
    if (f >= NFACE) return;
    int a = __ldg(&faces[3 * f + 0]);
    int b = __ldg(&faces[3 * f + 1]);
    int c = __ldg(&faces[3 * f + 2]);
    atomicAdd(&g_deg[a], 2);
    atomicAdd(&g_deg[b], 2);
    atomicAdd(&g_deg[c], 2);
}

// ---------------------------------------------------------------------------
// 3a. Per-block reduce of degrees (coalesced)
// ---------------------------------------------------------------------------
__global__ void scan_reduce_kernel() {
    __shared__ int sdata[SCAN_B / 32];
    int i = blockIdx.x * SCAN_B + threadIdx.x;
    int v = (i < NVERT) ? g_deg[i] : 0;
    for (int o = 16; o > 0; o >>= 1) v += __shfl_down_sync(0xffffffffu, v, o);
    if ((threadIdx.x & 31) == 0) sdata[threadIdx.x >> 5] = v;
    __syncthreads();
    if (threadIdx.x < 32) {
        int w = (threadIdx.x < SCAN_B / 32) ? sdata[threadIdx.x] : 0;
        for (int o = 16; o > 0; o >>= 1) w += __shfl_down_sync(0xffffffffu, w, o);
        if (threadIdx.x == 0) g_blocksum[blockIdx.x] = w;
    }
}

// ---------------------------------------------------------------------------
// 3b. Exclusive scan of block sums (parallel Hillis-Steele, one block)
// ---------------------------------------------------------------------------
__global__ void scan_spine_kernel() {
    __shared__ int s[256];
    int t = threadIdx.x;
    int v = (t < NBLK) ? g_blocksum[t] : 0;
    s[t] = v;
    __syncthreads();
    for (int d = 1; d < 256; d <<= 1) {
        int add = (t >= d) ? s[t - d] : 0;
        __syncthreads();
        s[t] += add;
        __syncthreads();
    }
    if (t < NBLK) g_blockoff[t] = s[t] - v;   // exclusive
}

// ---------------------------------------------------------------------------
// 3c. In-block exclusive scan + global offset (coalesced)
// ---------------------------------------------------------------------------
__global__ void scan_final_kernel() {
    __shared__ int s[SCAN_B];
    int t = threadIdx.x;
    int i = blockIdx.x * SCAN_B + t;
    int v = (i < NVERT) ? g_deg[i] : 0;
    s[t] = v;
    __syncthreads();
    for (int d = 1; d < SCAN_B; d <<= 1) {
        int add = (t >= d) ? s[t - d] : 0;
        __syncthreads();
        s[t] += add;
        __syncthreads();
    }
    if (i < NVERT) {
        int excl = s[t] - v + g_blockoff[blockIdx.x];
        g_start[i] = excl;
        g_cursor[i] = excl;
    }
}

// ---------------------------------------------------------------------------
// 4. Fill adjacency lists. Cursors are always even, so each 2-entry append
//    is one aligned int2 store.
// ---------------------------------------------------------------------------
__global__ void fill_adj_kernel(const int* __restrict__ faces) {
    int f = blockIdx.x * blockDim.x + threadIdx.x;
    if (f >= NFACE) return;
    int a = __ldg(&faces[3 * f + 0]);
    int b = __ldg(&faces[3 * f + 1]);
    int c = __ldg(&faces[3 * f + 2]);

    int pa = atomicAdd(&g_cursor[a], 2);
    g_adj2[pa >> 1] = make_int2(b, c);
    int pb = atomicAdd(&g_cursor[b], 2);
    g_adj2[pb >> 1] = make_int2(a, c);
    int pc = atomicAdd(&g_cursor[c], 2);
    g_adj2[pc >> 1] = make_int2(a, b);
}

// ---------------------------------------------------------------------------
// 5. SMEM-tiled transpose: vert [B][N][3] -> g_vert3 [N][B][3]
// ---------------------------------------------------------------------------
#define TVERTS 32
__global__ void __launch_bounds__(256)
transpose_kernel(const float* __restrict__ vert) {
    __shared__ float sm[BATCH][TVERTS * 3 + 1];
    int v0 = blockIdx.x * TVERTS;
    int nv = NVERT - v0;
    if (nv > TVERTS) nv = TVERTS;
    int nfl = nv * 3;

    for (int i = threadIdx.x; i < BATCH * TVERTS * 3; i += 256) {
        int b = i / (TVERTS * 3);
        int r = i % (TVERTS * 3);
        if (r < nfl) {
            sm[b][r] = vert[((size_t)b * NVERT + v0) * 3 + r];
        }
    }
    __syncthreads();

    float* dst = g_vert3 + (size_t)v0 * (BATCH * 3);
    for (int i = threadIdx.x; i < nv * BATCH * 3; i += 256) {
        int vv = i / (BATCH * 3);
        int r = i % (BATCH * 3);
        int b = r / 3;
        int c = r % 3;
        dst[i] = sm[b][vv * 3 + c];
    }
}

// ---------------------------------------------------------------------------
// 6. Gather + finalize: one warp per vertex, 32 vertices per 1024-thread block.
//    lane l: batch b = l&15, parity j = l>>4.
//    Each parity half-warp consumes one int2 adjacency PAIR per iteration
//    (2 neighbor rows, 6 independent vertex loads per lane -> high MLP).
//    Output staged in SMEM and flushed coalesced (128B runs per batch row).
// ---------------------------------------------------------------------------
__global__ void __launch_bounds__(1024)
gather_kernel(float* __restrict__ out) {
    __shared__ float sout[BATCH][GW + 1];   // +1 pad: conflict-free column writes

    int warpId = threadIdx.x >> 5;
    int v = blockIdx.x * GW + warpId;
    int lane = threadIdx.x & 31;
    int b = lane & 15;
    int j = lane >> 4;

    if (v < NVERT) {
        int d = g_deg[v];
        int pairs = d >> 1;
        const int2* __restrict__ adj = g_adj2 + (g_start[v] >> 1);

        float ax = 0.f, ay = 0.f, az = 0.f;

        int kp = j;
        int2 uu = (kp < pairs) ? __ldg(&adj[kp]) : make_int2(0, 0);
        while (kp < pairs) {
            int kn = kp + 2;
            int2 un = (kn < pairs) ? __ldg(&adj[kn]) : make_int2(0, 0);  // prefetch
            const float* __restrict__ p0 = g_vert3 + ((size_t)uu.x * (BATCH * 3) + b * 3);
            const float* __restrict__ p1 = g_vert3 + ((size_t)uu.y * (BATCH * 3) + b * 3);
            float x0 = __ldg(&p0[0]), y0 = __ldg(&p0[1]), z0 = __ldg(&p0[2]);
            float x1 = __ldg(&p1[0]), y1 = __ldg(&p1[1]), z1 = __ldg(&p1[2]);
            ax += x0 + x1;
            ay += y0 + y1;
            az += z0 + z1;
            uu = un;
            kp = kn;
        }

        ax += __shfl_xor_sync(0xffffffffu, ax, 16);
        ay += __shfl_xor_sync(0xffffffffu, ay, 16);
        az += __shfl_xor_sync(0xffffffffu, az, 16);

        if (j == 0) {
            float inv = 1.0f / fmaxf((float)d, 1.0f);
            const float* __restrict__ p = g_vert3 + ((size_t)v * (BATCH * 3) + b * 3);
            float lx = ax * inv - p[0];
            float ly = ay * inv - p[1];
            float lz = az * inv - p[2];
            sout[b][warpId] = sqrtf(lx * lx + ly * ly + lz * lz);
        }
    }
    __syncthreads();

    // Coalesced flush: thread t -> (batch t/32, vertex-offset t%32)
    int t = threadIdx.x;
    if (t < BATCH * GW) {
        int bb = t >> 5;
        int i = t & 31;
        int vv = blockIdx.x * GW + i;
        if (vv < NVERT) {
            out[(size_t)bb * NVERT + vv] = sout[bb][i];
        }
    }
}

// ---------------------------------------------------------------------------
extern "C" void kernel_launch(void* const* d_in, const int* in_sizes, int n_in,
                              void* d_out, int out_size) {
    const float* vert = (const float*)d_in[0];
    const int* faces = (const int*)d_in[1];
    float* out = (float*)d_out;

    const int T = 256;

    zero_deg_kernel<<<(NVERT + T - 1) / T, T>>>();
    count_deg_kernel<<<(NFACE + T - 1) / T, T>>>(faces);

    scan_reduce_kernel<<<NBLK, SCAN_B>>>();
    scan_spine_kernel<<<1, 256>>>();
    scan_final_kernel<<<NBLK, SCAN_B>>>();

    fill_adj_kernel<<<(NFACE + T - 1) / T, T>>>(faces);

    transpose_kernel<<<(NVERT + TVERTS - 1) / TVERTS, T>>>(vert);

    gather_kernel<<<(NVERT + GW - 1) / GW, 1024>>>(out);
}

// round 7
// speedup vs baseline: 1.0908x; 1.0908x over previous
#include <cuda_runtime.h>
#include <cstddef>

#define BATCH 16
#define NVERT 250000
#define NFACE 500000
#define NADJ  (6 * NFACE)          // 3,000,000 adjacency entries
#define SCAN_B 1024
#define NBLK ((NVERT + SCAN_B - 1) / SCAN_B)   // 245
#define ROWF 64                    // floats per vertex row (48 used + 16 pad)

// ---------------------------------------------------------------------------
// Device scratch (static; no runtime allocation allowed)
// ---------------------------------------------------------------------------
__device__ int    g_deg[NVERT];
__device__ int    g_start[NVERT];
__device__ int    g_cursor[NVERT];
__device__ int2   g_adj2[NADJ / 2];                 // pairs (all offsets even)
__device__ int    g_blocksum[NBLK];
__device__ int    g_blockoff[NBLK];
// [v][64]: x0..x15 | y0..y15 | z0..z15 | pad. 256B rows, line-aligned.
__device__ __align__(256) float g_vertp[(size_t)NVERT * ROWF];

// ---------------------------------------------------------------------------
// 1. Zero degrees
// ---------------------------------------------------------------------------
__global__ void zero_deg_kernel() {
    int i = blockIdx.x * blockDim.x + threadIdx.x;
    if (i < NVERT) g_deg[i] = 0;
}

// ---------------------------------------------------------------------------
// 2. Count degrees
// ---------------------------------------------------------------------------
__global__ void count_deg_kernel(const int* __restrict__ faces) {
    int f = blockIdx.x * blockDim.x + threadIdx.x;
    if (f >= NFACE) return;
    int a = __ldg(&faces[3 * f + 0]);
    int b = __ldg(&faces[3 * f + 1]);
    int c = __ldg(&faces[3 * f + 2]);
    atomicAdd(&g_deg[a], 2);
    atomicAdd(&g_deg[b], 2);
    atomicAdd(&g_deg[c], 2);
}

// ---------------------------------------------------------------------------
// 3a. Per-block reduce of degrees (coalesced)
// ---------------------------------------------------------------------------
__global__ void scan_reduce_kernel() {
    __shared__ int sdata[SCAN_B / 32];
    int i = blockIdx.x * SCAN_B + threadIdx.x;
    int v = (i < NVERT) ? g_deg[i] : 0;
    for (int o = 16; o > 0; o >>= 1) v += __shfl_down_sync(0xffffffffu, v, o);
    if ((threadIdx.x & 31) == 0) sdata[threadIdx.x >> 5] = v;
    __syncthreads();
    if (threadIdx.x < 32) {
        int w = (threadIdx.x < SCAN_B / 32) ? sdata[threadIdx.x] : 0;
        for (int o = 16; o > 0; o >>= 1) w += __shfl_down_sync(0xffffffffu, w, o);
        if (threadIdx.x == 0) g_blocksum[blockIdx.x] = w;
    }
}

// ---------------------------------------------------------------------------
// 3b. Exclusive scan of block sums (parallel Hillis-Steele, one block)
// ---------------------------------------------------------------------------
__global__ void scan_spine_kernel() {
    __shared__ int s[256];
    int t = threadIdx.x;
    int v = (t < NBLK) ? g_blocksum[t] : 0;
    s[t] = v;
    __syncthreads();
    for (int d = 1; d < 256; d <<= 1) {
        int add = (t >= d) ? s[t - d] : 0;
        __syncthreads();
        s[t] += add;
        __syncthreads();
    }
    if (t < NBLK) g_blockoff[t] = s[t] - v;   // exclusive
}

// ---------------------------------------------------------------------------
// 3c. In-block exclusive scan + global offset (coalesced)
// ---------------------------------------------------------------------------
__global__ void scan_final_kernel() {
    __shared__ int s[SCAN_B];
    int t = threadIdx.x;
    int i = blockIdx.x * SCAN_B + t;
    int v = (i < NVERT) ? g_deg[i] : 0;
    s[t] = v;
    __syncthreads();
    for (int d = 1; d < SCAN_B; d <<= 1) {
        int add = (t >= d) ? s[t - d] : 0;
        __syncthreads();
        s[t] += add;
        __syncthreads();
    }
    if (i < NVERT) {
        int excl = s[t] - v + g_blockoff[blockIdx.x];
        g_start[i] = excl;
        g_cursor[i] = excl;
    }
}

// ---------------------------------------------------------------------------
// 4. Fill adjacency lists (cursors always even -> aligned int2 stores)
// ---------------------------------------------------------------------------
__global__ void fill_adj_kernel(const int* __restrict__ faces) {
    int f = blockIdx.x * blockDim.x + threadIdx.x;
    if (f >= NFACE) return;
    int a = __ldg(&faces[3 * f + 0]);
    int b = __ldg(&faces[3 * f + 1]);
    int c = __ldg(&faces[3 * f + 2]);

    int pa = atomicAdd(&g_cursor[a], 2);
    g_adj2[pa >> 1] = make_int2(b, c);
    int pb = atomicAdd(&g_cursor[b], 2);
    g_adj2[pb >> 1] = make_int2(a, c);
    int pc = atomicAdd(&g_cursor[c], 2);
    g_adj2[pc >> 1] = make_int2(a, b);
}

// ---------------------------------------------------------------------------
// 5. SMEM-tiled transpose: vert [B][N][3] -> g_vertp [N][64] component-major.
//    Reads coalesced; writes: 192B runs per 256B row (pad skipped).
// ---------------------------------------------------------------------------
#define TVERTS 32
__global__ void __launch_bounds__(256)
transpose_kernel(const float* __restrict__ vert) {
    __shared__ float sm[BATCH][TVERTS * 3 + 1];
    int v0 = blockIdx.x * TVERTS;
    int nv = NVERT - v0;
    if (nv > TVERTS) nv = TVERTS;
    int nfl = nv * 3;

    for (int i = threadIdx.x; i < BATCH * TVERTS * 3; i += 256) {
        int b = i / (TVERTS * 3);
        int r = i % (TVERTS * 3);
        if (r < nfl) {
            sm[b][r] = vert[((size_t)b * NVERT + v0) * 3 + r];
        }
    }
    __syncthreads();

    // Write: row layout [x0..x15 | y0..y15 | z0..z15 | pad]
    float* dst = g_vertp + (size_t)v0 * ROWF;
    for (int i = threadIdx.x; i < nv * ROWF; i += 256) {
        int vv = i >> 6;
        int r = i & 63;
        int c = r >> 4;      // component
        int b = r & 15;      // batch
        if (c < 3) {
            dst[i] = sm[b][vv * 3 + c];
        }
    }
}

// ---------------------------------------------------------------------------
// 6. Gather + finalize: one warp per vertex (256-thread blocks, warps
//    independent). lane l: batch b = l&15, parity j = l>>4.
//    Per entry, 3 scalar LDGs hit 64B component segments inside 256B-aligned
//    rows -> 3 line-wavefronts per entry, 192B sector traffic per entry.
// ---------------------------------------------------------------------------
__global__ void __launch_bounds__(256)
gather_kernel(float* __restrict__ out) {
    int w = (blockIdx.x * blockDim.x + threadIdx.x) >> 5;
    if (w >= NVERT) return;
    int v = w;
    int lane = threadIdx.x & 31;
    int b = lane & 15;
    int j = lane >> 4;

    int s = g_start[v];
    int d = g_deg[v];

    float ax = 0.f, ay = 0.f, az = 0.f;
    const int* __restrict__ adj = reinterpret_cast<const int*>(g_adj2) + s;

    int k = j;
    int u = (k < d) ? __ldg(&adj[k]) : 0;
    while (k < d) {
        int k2 = k + 2;
        int u_next = (k2 < d) ? __ldg(&adj[k2]) : 0;   // prefetch: breaks chain
        const float* __restrict__ p = g_vertp + (size_t)u * ROWF;
        ax += __ldg(&p[b]);
        ay += __ldg(&p[16 + b]);
        az += __ldg(&p[32 + b]);
        u = u_next;
        k = k2;
    }

    ax += __shfl_xor_sync(0xffffffffu, ax, 16);
    ay += __shfl_xor_sync(0xffffffffu, ay, 16);
    az += __shfl_xor_sync(0xffffffffu, az, 16);

    if (j == 0) {
        float inv = 1.0f / fmaxf((float)d, 1.0f);
        const float* __restrict__ p = g_vertp + (size_t)v * ROWF;
        float lx = ax * inv - __ldg(&p[b]);
        float ly = ay * inv - __ldg(&p[16 + b]);
        float lz = az * inv - __ldg(&p[32 + b]);
        out[(size_t)b * NVERT + v] = sqrtf(lx * lx + ly * ly + lz * lz);
    }
}

// ---------------------------------------------------------------------------
extern "C" void kernel_launch(void* const* d_in, const int* in_sizes, int n_in,
                              void* d_out, int out_size) {
    const float* vert = (const float*)d_in[0];
    const int* faces = (const int*)d_in[1];
    float* out = (float*)d_out;

    const int T = 256;

    zero_deg_kernel<<<(NVERT + T - 1) / T, T>>>();
    count_deg_kernel<<<(NFACE + T - 1) / T, T>>>(faces);

    scan_reduce_kernel<<<NBLK, SCAN_B>>>();
    scan_spine_kernel<<<1, 256>>>();
    scan_final_kernel<<<NBLK, SCAN_B>>>();

    fill_adj_kernel<<<(NFACE + T - 1) / T, T>>>(faces);

    transpose_kernel<<<(NVERT + TVERTS - 1) / TVERTS, T>>>(vert);

    {
        int warps_per_block = T / 32;  // 8
        int blocks = (NVERT + warps_per_block - 1) / warps_per_block;
        gather_kernel<<<blocks, T>>>(out);
    }
}

// round 8
// speedup vs baseline: 1.1944x; 1.0950x over previous
#include <cuda_runtime.h>
#include <cstddef>

#define BATCH 16
#define NVERT 250000
#define NFACE 500000
#define MAXD  64                  // max adjacency entries per vertex (2*Poisson(6) tail-safe)

// ---------------------------------------------------------------------------
// Device scratch (static; no runtime allocation allowed)
// ---------------------------------------------------------------------------
__device__ int   g_deg[NVERT];
// Fixed-stride adjacency: row v at g_adjf[v*MAXD], 256B-aligned rows
__device__ __align__(256) int g_adjf[(size_t)NVERT * MAXD];         // 64 MB
// [v][b][xyz] packed float3 rows: 48 floats = 192 B per vertex, 48 MB
__device__ float g_vert3[(size_t)NVERT * BATCH * 3];
// gather output staged [v][b] for coalesced writes, 16 MB
__device__ float g_outvb[(size_t)NVERT * BATCH];

// ---------------------------------------------------------------------------
// 1. Zero degrees
// ---------------------------------------------------------------------------
__global__ void zero_deg_kernel() {
    int i = blockIdx.x * blockDim.x + threadIdx.x;
    if (i < NVERT) g_deg[i] = 0;
}

// ---------------------------------------------------------------------------
// 2. Fused count + fill: atomicAdd returns the slot; no scan needed.
//    Slots are always even -> aligned int2 stores.
// ---------------------------------------------------------------------------
__global__ void fill_kernel(const int* __restrict__ faces) {
    int f = blockIdx.x * blockDim.x + threadIdx.x;
    if (f >= NFACE) return;
    int a = __ldg(&faces[3 * f + 0]);
    int b = __ldg(&faces[3 * f + 1]);
    int c = __ldg(&faces[3 * f + 2]);

    int pa = atomicAdd(&g_deg[a], 2);
    *reinterpret_cast<int2*>(&g_adjf[(size_t)a * MAXD + pa]) = make_int2(b, c);
    int pb = atomicAdd(&g_deg[b], 2);
    *reinterpret_cast<int2*>(&g_adjf[(size_t)b * MAXD + pb]) = make_int2(a, c);
    int pc = atomicAdd(&g_deg[c], 2);
    *reinterpret_cast<int2*>(&g_adjf[(size_t)c * MAXD + pc]) = make_int2(a, b);
}

// ---------------------------------------------------------------------------
// 3. SMEM-tiled transpose: vert [B][N][3] -> g_vert3 [N][B][3]
// ---------------------------------------------------------------------------
#define TVERTS 32
__global__ void __launch_bounds__(256)
transpose_kernel(const float* __restrict__ vert) {
    __shared__ float sm[BATCH][TVERTS * 3 + 1];
    int v0 = blockIdx.x * TVERTS;
    int nv = NVERT - v0;
    if (nv > TVERTS) nv = TVERTS;
    int nfl = nv * 3;

    for (int i = threadIdx.x; i < BATCH * TVERTS * 3; i += 256) {
        int b = i / (TVERTS * 3);
        int r = i % (TVERTS * 3);
        if (r < nfl) {
            sm[b][r] = vert[((size_t)b * NVERT + v0) * 3 + r];
        }
    }
    __syncthreads();

    float* dst = g_vert3 + (size_t)v0 * (BATCH * 3);
    for (int i = threadIdx.x; i < nv * BATCH * 3; i += 256) {
        int vv = i / (BATCH * 3);
        int r = i % (BATCH * 3);
        int b = r / 3;
        int c = r % 3;
        dst[i] = sm[b][vv * 3 + c];
    }
}

// ---------------------------------------------------------------------------
// 4. Gather + finalize: one warp per vertex, independent warps (256-thread
//    blocks). lane l: batch b = l&15, parity j = l>>4; half-warp per neighbor
//    192B row. Output written coalesced to g_outvb (64B run per warp).
// ---------------------------------------------------------------------------
__global__ void __launch_bounds__(256)
gather_kernel() {
    int w = (blockIdx.x * blockDim.x + threadIdx.x) >> 5;
    if (w >= NVERT) return;
    int v = w;
    int lane = threadIdx.x & 31;
    int b = lane & 15;
    int j = lane >> 4;

    int d = g_deg[v];

    float ax = 0.f, ay = 0.f, az = 0.f;
    const int* __restrict__ adj = g_adjf + (size_t)v * MAXD;

    int k = j;
    int u = (k < d) ? __ldg(&adj[k]) : 0;
    while (k < d) {
        int k2 = k + 2;
        int u_next = (k2 < d) ? __ldg(&adj[k2]) : 0;   // prefetch: breaks chain
        const float* __restrict__ p = g_vert3 + ((size_t)u * (BATCH * 3) + b * 3);
        ax += __ldg(&p[0]);
        ay += __ldg(&p[1]);
        az += __ldg(&p[2]);
        u = u_next;
        k = k2;
    }

    ax += __shfl_xor_sync(0xffffffffu, ax, 16);
    ay += __shfl_xor_sync(0xffffffffu, ay, 16);
    az += __shfl_xor_sync(0xffffffffu, az, 16);

    if (j == 0) {
        float inv = 1.0f / fmaxf((float)d, 1.0f);
        const float* __restrict__ p = g_vert3 + ((size_t)v * (BATCH * 3) + b * 3);
        float lx = ax * inv - p[0];
        float ly = ay * inv - p[1];
        float lz = az * inv - p[2];
        // coalesced: lanes 0..15 write 16 consecutive floats (64B run)
        g_outvb[(size_t)v * BATCH + b] = sqrtf(lx * lx + ly * ly + lz * lz);
    }
}

// ---------------------------------------------------------------------------
// 5. Output transpose: g_outvb [N][B] -> out [B][N], both sides coalesced.
//    Block: 64 vertices x 16 batches.
// ---------------------------------------------------------------------------
#define OVERTS 64
__global__ void __launch_bounds__(256)
out_transpose_kernel(float* __restrict__ out) {
    __shared__ float sm[OVERTS][BATCH + 1];
    int v0 = blockIdx.x * OVERTS;
    int nv = NVERT - v0;
    if (nv > OVERTS) nv = OVERTS;

    // Coalesced read: consecutive tid -> consecutive g_outvb addresses
    for (int i = threadIdx.x; i < nv * BATCH; i += 256) {
        int vv = i >> 4;
        int b = i & 15;
        sm[vv][b] = g_outvb[(size_t)(v0 + vv) * BATCH + b];
    }
    __syncthreads();

    // Coalesced write: per batch row, run of nv consecutive floats
    for (int i = threadIdx.x; i < BATCH * OVERTS; i += 256) {
        int b = i >> 6;         // i / 64
        int vv = i & 63;
        if (vv < nv) {
            out[(size_t)b * NVERT + (v0 + vv)] = sm[vv][b];
        }
    }
}

// ---------------------------------------------------------------------------
extern "C" void kernel_launch(void* const* d_in, const int* in_sizes, int n_in,
                              void* d_out, int out_size) {
    const float* vert = (const float*)d_in[0];
    const int* faces = (const int*)d_in[1];
    float* out = (float*)d_out;

    const int T = 256;

    zero_deg_kernel<<<(NVERT + T - 1) / T, T>>>();
    fill_kernel<<<(NFACE + T - 1) / T, T>>>(faces);

    transpose_kernel<<<(NVERT + TVERTS - 1) / TVERTS, T>>>(vert);

    {
        int warps_per_block = T / 32;  // 8
        int blocks = (NVERT + warps_per_block - 1) / warps_per_block;
        gather_kernel<<<blocks, T>>>();
    }

    out_transpose_kernel<<<(NVERT + OVERTS - 1) / OVERTS, T>>>(out);
}